// round 5
// baseline (speedup 1.0000x reference)
#include <cuda_runtime.h>
#include <cstdint>

// CTC batch cost (Keras ctc_batch_cost, full lengths).
// B=64, T=2048, C=128 (blank=127), L=256, S=2L+1=513.
//
// 2-CTA cluster per batch (128 CTAs). rank0 owns states [0,272); rank1
// computes [240,513) with a 32-state decaying halo refreshed every 16 steps
// via st.shared::cluster + cluster barrier.
//
// R5: alpha lives in REGISTERS (one state per thread). Neighbors alpha[s-1],
// alpha[s-2] come from __shfl_up_sync (warp-synchronous, no barrier); only
// warp-boundary values (lanes 30/31) go through shared, double-buffered by
// step parity, covered by the one __syncthreads per step. Log2-domain lse3
// (3x EX2 + 1x LG2 on MUFU). Frame log-probs double-buffered in shared with
// prefetch distance 4. y_true is int32.

#define CTC_B 64
#define CTC_T 2048
#define CTC_C 128
#define CTC_L 256
#define NEGF (-1e30f)
#define EPSF (1e-7f)
#define LN2F (0.69314718055994530942f)

#define SPLIT 272       // rank0 owns [0,272)
#define HALO  32        // rank1 redundant states [240,272)
#define NTHR  288       // 9 warps
#define NW    9

__device__ __forceinline__ float ex2f_(float x) {
    float r; asm("ex2.approx.ftz.f32 %0, %1;" : "=f"(r) : "f"(x)); return r;
}
__device__ __forceinline__ float lg2f_(float x) {
    float r; asm("lg2.approx.ftz.f32 %0, %1;" : "=f"(r) : "f"(x)); return r;
}
__device__ __forceinline__ uint32_t smem_u32_(const void* p) {
    uint32_t a;
    asm("{ .reg .u64 t; cvta.to.shared.u64 t, %1; cvt.u32.u64 %0, t; }"
        : "=r"(a) : "l"(p));
    return a;
}

__global__ __launch_bounds__(NTHR, 1) __cluster_dims__(2, 1, 1)
void ctc_forward_kernel(const int* __restrict__ y_true,
                        const float* __restrict__ y_pred,
                        float* __restrict__ out) {
    __shared__ float s_lp[2][CTC_C];      // log2(y_pred[t]+eps), double buffered
    __shared__ float s_bnd[2][NW + 1][2]; // [parity][warp row][{s-2,s-1}]; row0 = NEG
    __shared__ float s_halo[2][HALO];     // cluster mailbox (rank1 side)
    __shared__ float s_fin[2];

    const int tid  = threadIdx.x;
    const int lane = tid & 31;
    const int wid  = tid >> 5;
    uint32_t rank;
    asm("mov.u32 %0, %%cluster_ctarank;" : "=r"(rank));
    const int b = blockIdx.x >> 1;

    const int*   lab = y_true + b * CTC_L;
    const float* Y   = y_pred + (size_t)b * CTC_T * CTC_C;

    const int  s      = rank ? (240 + tid) : tid;
    const bool active = rank ? (tid < 273) : (tid < SPLIT);

    int cls = CTC_C - 1, skip = 0;
    if (active && (s & 1)) {
        int i = s >> 1;
        cls  = lab[i] & 127;
        skip = (s >= 3 && cls != (lab[i - 1] & 127)) ? 1 : 0;
    }

    // boundary slots: init ALL to NEG (alpha0 boundary lanes are all NEG too,
    // so no explicit publish of parity 0 is needed)
    if (tid < 2 * (NW + 1) * 2) ((float*)s_bnd)[tid] = NEGF;

    // alpha0 in register
    float cur = NEGF;
    if (rank == 0) {
        if (tid == 0) cur = lg2f_(Y[CTC_C - 1] + EPSF);
        else if (tid == 1) cur = lg2f_(Y[lab[0] & 127] + EPSF);
    }

    // remote mailbox addresses for rank0 senders (states 240..271)
    uint32_t rh0 = 0, rh1 = 0;
    if (rank == 0 && tid >= 240 && tid < 272) {
        uint32_t l0 = smem_u32_(&s_halo[0][tid - 240]);
        uint32_t l1 = smem_u32_(&s_halo[1][tid - 240]);
        asm("mapa.shared::cluster.u32 %0, %1, %2;" : "=r"(rh0) : "r"(l0), "r"(1));
        asm("mapa.shared::cluster.u32 %0, %1, %2;" : "=r"(rh1) : "r"(l1), "r"(1));
    }

    // prologue: lp for frame 1, prefetch frames 2..5
    float r0 = 0.f, r1 = 0.f, r2 = 0.f, r3 = 0.f;
    if (tid < CTC_C) {
        s_lp[1][tid] = lg2f_(Y[CTC_C + tid] + EPSF);
        r0 = Y[2 * CTC_C + tid];
        r1 = Y[3 * CTC_C + tid];
        r2 = Y[4 * CTC_C + tid];
        r3 = Y[5 * CTC_C + tid];
    }
    __syncthreads();

#define LOADF(t) Y[(size_t)((t) < CTC_T ? (t) : (CTC_T - 1)) * CTC_C + tid]

    // CBv = (t)&1 as a literal. Step t: consume alpha_{t-1} (boundary parity
    // 1-CBv), produce alpha_t (publish boundary parity CBv).
#define STEP(t, CBv, r) do {                                                   \
        float lpv = s_lp[(CBv)][cls];                                          \
        float bv  = __shfl_up_sync(0xffffffffu, cur, 1);                       \
        float cs  = __shfl_up_sync(0xffffffffu, cur, 2);                       \
        if (lane < 2) {                                                        \
            float bb = s_bnd[1 - (CBv)][wid][1];                               \
            cs = s_bnd[1 - (CBv)][wid][lane];                                  \
            if (lane == 0) bv = bb;                                            \
        }                                                                      \
        float cv  = skip ? cs : NEGF;                                          \
        float m   = fmaxf(cur, fmaxf(bv, cv));                                 \
        float sum = (ex2f_(cur - m) + ex2f_(bv - m)) + ex2f_(cv - m);          \
        cur = (m + lpv) + lg2f_(sum);                                          \
        if (lane >= 30) s_bnd[(CBv)][wid + 1][lane - 30] = cur;                \
        if (tid < CTC_C) {                                                     \
            s_lp[1 - (CBv)][tid] = lg2f_((r) + EPSF);                          \
            (r) = LOADF((t) + 5);                                              \
        }                                                                      \
        __syncthreads();                                                       \
    } while (0)

    // main recurrence: t = 1..2047, unrolled by 4; cluster exchange every 16
    for (int t = 1; t + 3 <= CTC_T - 1; t += 4) {
        STEP(t,     1, r0);
        STEP(t + 1, 0, r1);
        STEP(t + 2, 1, r2);
        STEP(t + 3, 0, r3);

        if (((t + 3) & 15) == 0) {
            // cur = alpha_{t+3}; (t+3)&1 == 0, so boundary parity 0 is current
            int buf = ((t + 3) >> 4) & 1;
            if (rank == 0 && tid >= 240 && tid < 272) {
                uint32_t ra = buf ? rh1 : rh0;
                asm volatile("st.shared::cluster.f32 [%0], %1;"
                             :: "r"(ra), "f"(cur) : "memory");
            }
            asm volatile("barrier.cluster.arrive.aligned;" ::: "memory");
            asm volatile("barrier.cluster.wait.aligned;"   ::: "memory");
            if (rank == 1) {
                if (tid < HALO) cur = s_halo[buf][tid];
                // re-publish repaired boundary of warp 0 (states 270,271)
                // into parity 0, else next step corrupts states 272,273
                if (wid == 0 && lane >= 30) s_bnd[0][1][lane - 30] = cur;
                __syncthreads();
            }
        }
    }
    // tail: t = 2045, 2046, 2047
    STEP(CTC_T - 3, 1, r0);
    STEP(CTC_T - 2, 0, r1);
    STEP(CTC_T - 1, 1, r2);

#undef STEP
#undef LOADF

    // final: rank1 holds state 511 in tid 271, state 512 in tid 272
    if (rank == 1) {
        if (tid == 271) s_fin[0] = cur;
        if (tid == 272) s_fin[1] = cur;
        __syncthreads();
        if (tid == 0) {
            float a = s_fin[1], c = s_fin[0];
            float m = fmaxf(a, c);
            float l2 = m + lg2f_(ex2f_(a - m) + ex2f_(c - m));
            out[b] = -l2 * LN2F;
        }
    }
}

extern "C" void kernel_launch(void* const* d_in, const int* in_sizes, int n_in,
                              void* d_out, int out_size) {
    const int*   y_true;
    const float* y_pred;
    if (in_sizes[0] == CTC_B * CTC_L) {
        y_true = (const int*)d_in[0];
        y_pred = (const float*)d_in[1];
    } else {
        y_true = (const int*)d_in[1];
        y_pred = (const float*)d_in[0];
    }
    float* out = (float*)d_out;

    ctc_forward_kernel<<<2 * CTC_B, NTHR>>>(y_true, y_pred, out);
}